// round 11
// baseline (speedup 1.0000x reference)
#include <cuda_runtime.h>
#include <cuda_bf16.h>
#include <cstdint>
#include <cstddef>

// ---------------------------------------------------------------------------
// BiAffine via legacy mma.sync bf16 3-product emulation (sm_100 base target).
//   dir1: Sh = S2@W1^T ; sc = S1@Sh^T ; A = softmax(sc) ; out1 = A@S2
//   dir2: Sh = S1@W2^T ; sc = S2@Sh^T ; A = softmax(sc) ; out2 = A@S1
// Every GEMM: D = Ah@Bh^T + Ah@Bl^T + Al@Bh^T with bf16 hi/lo splits.
// R11: inner loop rework — B-fragment double buffering (hide LDS latency
// behind mma groups) + XOR-derived ldmatrix addresses (cut alu/fma work).
// ---------------------------------------------------------------------------

#define BATCH 8
#define SEQ   2048
#define HDIM  1024

#define E1 ((size_t)BATCH * SEQ * HDIM)   // 16777216
#define EW ((size_t)HDIM * HDIM)          // 1048576
#define ES ((size_t)BATCH * SEQ * SEQ)    // 33554432

// ---- static scratch (no allocations allowed) ------------------------------
__device__ __nv_bfloat16 g_s1h[E1], g_s1l[E1], g_s2h[E1], g_s2l[E1];
__device__ __nv_bfloat16 g_s1th[E1], g_s1tl[E1], g_s2th[E1], g_s2tl[E1];
__device__ __nv_bfloat16 g_w1h[EW], g_w1l[EW], g_w2h[EW], g_w2l[EW];
__device__ __nv_bfloat16 g_shh[E1], g_shl[E1];
__device__ float         g_sc[ES];
__device__ __nv_bfloat16 g_ath[ES], g_atl[ES];

// ---------------------------------------------------------------------------
// helpers
// ---------------------------------------------------------------------------
__device__ __forceinline__ void cp16(uint32_t s, const void* g) {
    asm volatile("cp.async.cg.shared.global [%0], [%1], 16;" :: "r"(s), "l"(g));
}
__device__ __forceinline__ void cp_commit() {
    asm volatile("cp.async.commit_group;");
}
__device__ __forceinline__ void cp_wait1() {
    asm volatile("cp.async.wait_group 1;");
}

__device__ __forceinline__ void ldmx4(uint32_t* r, uint32_t addr) {
    asm volatile("ldmatrix.sync.aligned.m8n8.x4.shared.b16 {%0,%1,%2,%3}, [%4];"
                 : "=r"(r[0]), "=r"(r[1]), "=r"(r[2]), "=r"(r[3]) : "r"(addr));
}

__device__ __forceinline__ void mma16816(float* c, const uint32_t* a,
                                         uint32_t b0, uint32_t b1) {
    asm volatile(
        "mma.sync.aligned.m16n8k16.row.col.f32.bf16.bf16.f32 "
        "{%0,%1,%2,%3}, {%4,%5,%6,%7}, {%8,%9}, {%0,%1,%2,%3};"
        : "+f"(c[0]), "+f"(c[1]), "+f"(c[2]), "+f"(c[3])
        : "r"(a[0]), "r"(a[1]), "r"(a[2]), "r"(a[3]), "r"(b0), "r"(b1));
}

__device__ __forceinline__ void bsplit(float x, __nv_bfloat16& h, __nv_bfloat16& l) {
    h = __float2bfloat16_rn(x);
    l = __float2bfloat16_rn(x - __bfloat162float(h));
}

// ---------------------------------------------------------------------------
// GEMM: C[M,N] = Ah@Bh^T + Ah@Bl^T + Al@Bh^T  (bf16 mma.sync)
// A: [M,K] bf16 (hi,lo), B: [N,K] bf16 (hi,lo), K-major rows.
// CTA 128x128, 8 warps (4m x 2n), warp tile 32x64, BK=32, 3-stage cp.async.
// SMEM per stage 32KB: A rows [hi 64B | lo 64B] x128 (16KB), B same (16KB).
// Swizzle: physical 16B-chunk = logical ^ (row & 7). Since the logical chunk
// id = c0 | (k<<1) | (lo<<2) has disjoint bits, every ldmatrix address is
// (precomputed base + stage) ^ (k<<5) ^ (lo<<6).
// MODE 0: C0 = fp32.  MODE 1: C0 = bf16 hi, C1 = bf16 lo.
// ---------------------------------------------------------------------------
#define STAGE 32768
#define NSTG  3
#define SMEM_REQ (NSTG * STAGE + 1024)

template <int MODE>
__global__ __launch_bounds__(256, 2) void gemm3x(
    const __nv_bfloat16* __restrict__ Ah, const __nv_bfloat16* __restrict__ Al,
    const __nv_bfloat16* __restrict__ Bh, const __nv_bfloat16* __restrict__ Bl,
    void* __restrict__ C0v, void* __restrict__ C1v,
    int M, int N, int K, size_t sAb, size_t sBb, size_t sCb)
{
    extern __shared__ char smem[];
    const int tid  = threadIdx.x;
    const int wid  = tid >> 5;
    const int lane = tid & 31;
    const int wm   = wid >> 1;      // 0..3  (m)
    const int wn   = wid & 1;       // 0..1  (n)
    const int m0   = blockIdx.y * 128;
    const int n0   = blockIdx.x * 128;
    const int b    = blockIdx.z;

    Ah += (size_t)b * sAb;  Al += (size_t)b * sAb;
    Bh += (size_t)b * sBb;  Bl += (size_t)b * sBb;

    uint32_t sbase = (uint32_t)__cvta_generic_to_shared(smem);
    const uint32_t ST0 = (sbase + 1023) & ~1023u;

    const int T = K >> 5;           // K tiles of 32

    // fill chunk assignment: fc = 16B chunk (0..7), fr0 = row group base
    const int fc  = tid & 7;
    const int fr0 = tid >> 3;       // 0..31

    // stage index advances mod 3
    auto fill = [&](int kt, int s) {
        const uint32_t sa = ST0 + s * STAGE;
        const uint32_t sb = sa + 16384;
        const int kg = kt * 32 + (fc & 3) * 8;
#pragma unroll
        for (int i = 0; i < 4; i++) {
            int row = fr0 + i * 32;
            uint32_t so = (uint32_t)row * 128 + (uint32_t)(fc ^ (row & 7)) * 16;
            const __nv_bfloat16* ga = (fc < 4)
                ? Ah + (size_t)(m0 + row) * K + kg
                : Al + (size_t)(m0 + row) * K + kg;
            cp16(sa + so, ga);
            const __nv_bfloat16* gb = (fc < 4)
                ? Bh + (size_t)(n0 + row) * K + kg
                : Bl + (size_t)(n0 + row) * K + kg;
            cp16(sb + so, gb);
        }
        cp_commit();
    };

    // precomputed ldmatrix base offsets (relative to stage base sa):
    // A hi, k=0:  mr*128 + ((c0 ^ (mr&7)) * 16)
    // B hi, k=0:  16384 + nr*128 + ((c0 ^ (nr&7)) * 16)
    const int c0 = lane >> 4;
    uint32_t offA[2], offB[4];
#pragma unroll
    for (int mt = 0; mt < 2; mt++) {
        int mr = wm * 32 + mt * 16 + (lane & 15);
        offA[mt] = (uint32_t)mr * 128 + (uint32_t)(c0 ^ (mr & 7)) * 16;
    }
#pragma unroll
    for (int ng = 0; ng < 4; ng++) {
        int nr = wn * 64 + ng * 16 + (lane & 15);
        offB[ng] = 16384u + (uint32_t)nr * 128 + (uint32_t)(c0 ^ (nr & 7)) * 16;
    }

    float acc[2][8][4];
#pragma unroll
    for (int mt = 0; mt < 2; mt++)
#pragma unroll
        for (int nt = 0; nt < 8; nt++)
#pragma unroll
            for (int j = 0; j < 4; j++) acc[mt][nt][j] = 0.0f;

    fill(0, 0); fill(1, 1);

    int scur = 0;                   // stage of chunk kt
    int snext2 = 2;                 // stage for chunk kt+2
    for (int kt = 0; kt < T; kt++) {
        cp_wait1();
        __syncthreads();
        if (kt + 2 < T) fill(kt + 2, snext2); else cp_commit();

        const uint32_t sa = ST0 + scur * STAGE;
        scur = (scur == 2) ? 0 : scur + 1;
        snext2 = (snext2 == 2) ? 0 : snext2 + 1;

#pragma unroll
        for (int k = 0; k < 2; k++) {          // two k16 steps
            const uint32_t kx = (uint32_t)k << 5;
            uint32_t ah[2][4], al[2][4];
#pragma unroll
            for (int mt = 0; mt < 2; mt++) {
                uint32_t a0 = (sa + offA[mt]) ^ kx;
                ldmx4(ah[mt], a0);
                ldmx4(al[mt], a0 ^ 0x40u);
            }
            uint32_t bh[2][4], bl[2][4];       // double-buffered B frags
            {
                uint32_t b0 = (sa + offB[0]) ^ kx;
                ldmx4(bh[0], b0);
                ldmx4(bl[0], b0 ^ 0x40u);
            }
#pragma unroll
            for (int ng = 0; ng < 4; ng++) {
                const int cur = ng & 1, nxt = cur ^ 1;
                if (ng < 3) {                  // prefetch next n16 group
                    uint32_t b0 = (sa + offB[ng + 1]) ^ kx;
                    ldmx4(bh[nxt], b0);
                    ldmx4(bl[nxt], b0 ^ 0x40u);
                }
#pragma unroll
                for (int mt = 0; mt < 2; mt++)
#pragma unroll
                    for (int o = 0; o < 2; o++) {
                        const int nt = 2 * ng + o;
                        mma16816(acc[mt][nt], ah[mt], bh[cur][o], bh[cur][2 + o]);
                        mma16816(acc[mt][nt], ah[mt], bl[cur][o], bl[cur][2 + o]);
                        mma16816(acc[mt][nt], al[mt], bh[cur][o], bh[cur][2 + o]);
                    }
            }
        }
    }

    // ---- epilogue (accumulators -> global) ----
    const int gm0 = m0 + wm * 32;
    const int gn0 = n0 + wn * 64;
#pragma unroll
    for (int mt = 0; mt < 2; mt++) {
#pragma unroll
        for (int nt = 0; nt < 8; nt++) {
            int r  = gm0 + mt * 16 + (lane >> 2);
            int cc = gn0 + nt * 8 + 2 * (lane & 3);
            if (MODE == 0) {
                float* C0 = (float*)C0v + (size_t)b * sCb;
                *(float2*)(C0 + (size_t)r * N + cc) =
                    make_float2(acc[mt][nt][0], acc[mt][nt][1]);
                *(float2*)(C0 + (size_t)(r + 8) * N + cc) =
                    make_float2(acc[mt][nt][2], acc[mt][nt][3]);
            } else {
                __nv_bfloat16* CH = (__nv_bfloat16*)C0v + (size_t)b * sCb;
                __nv_bfloat16* CL = (__nv_bfloat16*)C1v + (size_t)b * sCb;
                __nv_bfloat16 h0, l0, h1, l1;
#pragma unroll
                for (int hh = 0; hh < 2; hh++) {
                    int rr = r + hh * 8;
                    bsplit(acc[mt][nt][2 * hh + 0], h0, l0);
                    bsplit(acc[mt][nt][2 * hh + 1], h1, l1);
                    *(__nv_bfloat162*)(CH + (size_t)rr * N + cc) =
                        __nv_bfloat162(h0, h1);
                    *(__nv_bfloat162*)(CL + (size_t)rr * N + cc) =
                        __nv_bfloat162(l0, l1);
                }
            }
        }
    }
}

// ---------------------------------------------------------------------------
// split fp32 -> bf16 hi/lo
// ---------------------------------------------------------------------------
__global__ __launch_bounds__(256) void split_bf16(
    const float* __restrict__ x, __nv_bfloat16* __restrict__ hi,
    __nv_bfloat16* __restrict__ lo, size_t n4)
{
    size_t i = (size_t)blockIdx.x * blockDim.x + threadIdx.x;
    size_t stride = (size_t)gridDim.x * blockDim.x;
    for (; i < n4; i += stride) {
        float4 v = ((const float4*)x)[i];
        __nv_bfloat16 h0, l0, h1, l1, h2, l2, h3, l3;
        bsplit(v.x, h0, l0); bsplit(v.y, h1, l1);
        bsplit(v.z, h2, l2); bsplit(v.w, h3, l3);
        ((__nv_bfloat162*)hi)[2 * i]     = __nv_bfloat162(h0, h1);
        ((__nv_bfloat162*)hi)[2 * i + 1] = __nv_bfloat162(h2, h3);
        ((__nv_bfloat162*)lo)[2 * i]     = __nv_bfloat162(l0, l1);
        ((__nv_bfloat162*)lo)[2 * i + 1] = __nv_bfloat162(l2, l3);
    }
}

// ---------------------------------------------------------------------------
// transpose + split: S[b][n][h] -> T{hi,lo}[b][h][n]   (bf16)
// ---------------------------------------------------------------------------
__global__ __launch_bounds__(256) void transpose_split(
    const float* __restrict__ S, __nv_bfloat16* __restrict__ Th,
    __nv_bfloat16* __restrict__ Tl)
{
    __shared__ float t[32][33];
    const int b  = blockIdx.z;
    const int h0 = blockIdx.x * 32;
    const int n0 = blockIdx.y * 32;
    const int tx = threadIdx.x, ty = threadIdx.y;
    const float* Sb = S + (size_t)b * SEQ * HDIM;
#pragma unroll
    for (int i = 0; i < 4; i++) {
        int r = ty + i * 8;
        t[r][tx] = Sb[(size_t)(n0 + r) * HDIM + h0 + tx];
    }
    __syncthreads();
    const size_t obase = (size_t)b * HDIM * SEQ;
#pragma unroll
    for (int i = 0; i < 4; i++) {
        int r = ty + i * 8;
        float v = t[tx][r];
        __nv_bfloat16 h, l;
        bsplit(v, h, l);
        size_t o = obase + (size_t)(h0 + r) * SEQ + n0 + tx;
        Th[o] = h;
        Tl[o] = l;
    }
}

// ---------------------------------------------------------------------------
// softmax rows (len 2048) + bf16 hi/lo split of probabilities
// ---------------------------------------------------------------------------
__global__ __launch_bounds__(256) void softmax_split(
    const float* __restrict__ S, __nv_bfloat16* __restrict__ Ph,
    __nv_bfloat16* __restrict__ Pl)
{
    const float* row = S + (size_t)blockIdx.x * SEQ;
    const int tid = threadIdx.x;
    const int lane = tid & 31, wrp = tid >> 5;
    __shared__ float red[8];

    float v[8];
    float4 v0 = *(const float4*)(row + tid * 8);
    float4 v1 = *(const float4*)(row + tid * 8 + 4);
    v[0]=v0.x; v[1]=v0.y; v[2]=v0.z; v[3]=v0.w;
    v[4]=v1.x; v[5]=v1.y; v[6]=v1.z; v[7]=v1.w;

    float m = v[0];
#pragma unroll
    for (int i = 1; i < 8; i++) m = fmaxf(m, v[i]);
#pragma unroll
    for (int o = 16; o > 0; o >>= 1) m = fmaxf(m, __shfl_xor_sync(~0u, m, o));
    if (lane == 0) red[wrp] = m;
    __syncthreads();
    m = red[0];
#pragma unroll
    for (int w = 1; w < 8; w++) m = fmaxf(m, red[w]);
    __syncthreads();

    float s = 0.0f;
#pragma unroll
    for (int i = 0; i < 8; i++) { v[i] = __expf(v[i] - m); s += v[i]; }
#pragma unroll
    for (int o = 16; o > 0; o >>= 1) s += __shfl_xor_sync(~0u, s, o);
    if (lane == 0) red[wrp] = s;
    __syncthreads();
    s = red[0];
#pragma unroll
    for (int w = 1; w < 8; w++) s += red[w];
    float inv = 1.0f / s;

    __nv_bfloat162* ph = (__nv_bfloat162*)(Ph + (size_t)blockIdx.x * SEQ + tid * 8);
    __nv_bfloat162* pl = (__nv_bfloat162*)(Pl + (size_t)blockIdx.x * SEQ + tid * 8);
#pragma unroll
    for (int i = 0; i < 4; i++) {
        __nv_bfloat16 h0, l0, h1, l1;
        bsplit(v[2 * i] * inv,     h0, l0);
        bsplit(v[2 * i + 1] * inv, h1, l1);
        ph[i] = __nv_bfloat162(h0, h1);
        pl[i] = __nv_bfloat162(l0, l1);
    }
}

// ---------------------------------------------------------------------------
// launch — order keeps launch index 3 (ncu-captured) on gemm3x<1> (proj1).
// ---------------------------------------------------------------------------
extern "C" void kernel_launch(void* const* d_in, const int* in_sizes, int n_in,
                              void* d_out, int out_size)
{
    const float* S1 = (const float*)d_in[0];
    const float* S2 = (const float*)d_in[1];
    const float* W1 = (const float*)d_in[2];
    const float* W2 = (const float*)d_in[3];

    float* out1 = (float*)d_out;
    float* out2 = out1 + E1;

    __nv_bfloat16 *s1h, *s1l, *s2h, *s2l, *s1th, *s1tl, *s2th, *s2tl;
    __nv_bfloat16 *w1h, *w1l, *w2h, *w2l, *shh, *shl, *ath, *atl;
    float* sc;
    cudaGetSymbolAddress((void**)&s1h,  g_s1h);
    cudaGetSymbolAddress((void**)&s1l,  g_s1l);
    cudaGetSymbolAddress((void**)&s2h,  g_s2h);
    cudaGetSymbolAddress((void**)&s2l,  g_s2l);
    cudaGetSymbolAddress((void**)&s1th, g_s1th);
    cudaGetSymbolAddress((void**)&s1tl, g_s1tl);
    cudaGetSymbolAddress((void**)&s2th, g_s2th);
    cudaGetSymbolAddress((void**)&s2tl, g_s2tl);
    cudaGetSymbolAddress((void**)&w1h,  g_w1h);
    cudaGetSymbolAddress((void**)&w1l,  g_w1l);
    cudaGetSymbolAddress((void**)&w2h,  g_w2h);
    cudaGetSymbolAddress((void**)&w2l,  g_w2l);
    cudaGetSymbolAddress((void**)&shh,  g_shh);
    cudaGetSymbolAddress((void**)&shl,  g_shl);
    cudaGetSymbolAddress((void**)&sc,   g_sc);
    cudaGetSymbolAddress((void**)&ath,  g_ath);
    cudaGetSymbolAddress((void**)&atl,  g_atl);

    cudaFuncSetAttribute(gemm3x<0>, cudaFuncAttributeMaxDynamicSharedMemorySize, SMEM_REQ);
    cudaFuncSetAttribute(gemm3x<1>, cudaFuncAttributeMaxDynamicSharedMemorySize, SMEM_REQ);

    const size_t sS  = (size_t)SEQ * HDIM;
    const size_t sSc = (size_t)SEQ * SEQ;

    dim3 blk(256);
    dim3 gProj(HDIM / 128, SEQ / 128, BATCH);   // N=1024, M=2048
    dim3 gScore(SEQ / 128, SEQ / 128, BATCH);   // N=2048, M=2048
    dim3 gPV(HDIM / 128, SEQ / 128, BATCH);     // N=1024, M=2048, K=2048
    dim3 tb(32, 8);
    dim3 tg(HDIM / 32, SEQ / 32, BATCH);

    // 0..2: the splits proj1/score1 need
    split_bf16<<<2048, 256>>>(S2, s2h, s2l, E1 / 4);                 // 0
    split_bf16<<<512,  256>>>(W1, w1h, w1l, EW / 4);                 // 1
    split_bf16<<<2048, 256>>>(S1, s1h, s1l, E1 / 4);                 // 2

    // 3: proj1  (ncu-captured launch)
    gemm3x<1><<<gProj, blk, SMEM_REQ>>>(                             // 3
        s2h, s2l, w1h, w1l, shh, shl, SEQ, HDIM, HDIM, sS, 0, sS);
    // 4: score1
    gemm3x<0><<<gScore, blk, SMEM_REQ>>>(                            // 4
        s1h, s1l, shh, shl, sc, nullptr, SEQ, SEQ, HDIM, sS, sS, sSc);

    split_bf16<<<512,  256>>>(W2, w2h, w2l, EW / 4);                 // 5
    transpose_split<<<tg, tb>>>(S2, s2th, s2tl);                     // 6
    softmax_split<<<BATCH * SEQ, 256>>>(sc, ath, atl);               // 7
    gemm3x<0><<<gPV, blk, SMEM_REQ>>>(                               // 8
        ath, atl, s2th, s2tl, out1, nullptr, SEQ, HDIM, SEQ, sSc, sS, sS);

    gemm3x<1><<<gProj, blk, SMEM_REQ>>>(                             // 9
        s1h, s1l, w2h, w2l, shh, shl, SEQ, HDIM, HDIM, sS, 0, sS);
    gemm3x<0><<<gScore, blk, SMEM_REQ>>>(                            // 10
        s2h, s2l, shh, shl, sc, nullptr, SEQ, SEQ, HDIM, sS, sS, sSc);
    transpose_split<<<tg, tb>>>(S1, s1th, s1tl);                     // 11
    softmax_split<<<BATCH * SEQ, 256>>>(sc, ath, atl);               // 12
    gemm3x<0><<<gPV, blk, SMEM_REQ>>>(                               // 13
        ath, atl, s1th, s1tl, out2, nullptr, SEQ, HDIM, SEQ, sSc, sS, sS);
}

// round 12
// speedup vs baseline: 1.3974x; 1.3974x over previous
#include <cuda_runtime.h>
#include <cuda_bf16.h>
#include <cuda_fp16.h>
#include <cstdint>
#include <cstddef>

// ---------------------------------------------------------------------------
// BiAffine, sm_100 base target (no tcgen05 at this compile target).
//   dir1: Sh = S2@W1^T ; sc = S1@Sh^T ; P = softmax(sc) ; out1 = P@S2
//   dir2: Sh = S1@W2^T ; sc = S2@Sh^T ; P = softmax(sc) ; out2 = P@S1
// proj/scores: bf16 hi/lo 3-product mma.sync (R9 kernel, best known).
// PV: single-product fp16 mma.sync (P in [0,1], S ~ N(0,1): fp16 suffices;
//     predicted rel_err contribution ~3e-4 < 1e-3 gate).
// ---------------------------------------------------------------------------

#define BATCH 8
#define SEQ   2048
#define HDIM  1024

#define E1 ((size_t)BATCH * SEQ * HDIM)   // 16777216
#define EW ((size_t)HDIM * HDIM)          // 1048576
#define ES ((size_t)BATCH * SEQ * SEQ)    // 33554432

// ---- static scratch (no allocations allowed) ------------------------------
__device__ __nv_bfloat16 g_s1h[E1], g_s1l[E1], g_s2h[E1], g_s2l[E1];
__device__ __nv_bfloat16 g_w1h[EW], g_w1l[EW], g_w2h[EW], g_w2l[EW];
__device__ __nv_bfloat16 g_shh[E1], g_shl[E1];
__device__ __half        g_s1t[E1], g_s2t[E1];   // transposed S, fp16
__device__ float         g_sc[ES];
__device__ __half        g_at[ES];               // softmax probs, fp16

// ---------------------------------------------------------------------------
// helpers
// ---------------------------------------------------------------------------
__device__ __forceinline__ void cp16(uint32_t s, const void* g) {
    asm volatile("cp.async.cg.shared.global [%0], [%1], 16;" :: "r"(s), "l"(g));
}
__device__ __forceinline__ void cp_commit() {
    asm volatile("cp.async.commit_group;");
}
__device__ __forceinline__ void cp_wait1() {
    asm volatile("cp.async.wait_group 1;");
}

__device__ __forceinline__ void ldmx4(uint32_t* r, uint32_t addr) {
    asm volatile("ldmatrix.sync.aligned.m8n8.x4.shared.b16 {%0,%1,%2,%3}, [%4];"
                 : "=r"(r[0]), "=r"(r[1]), "=r"(r[2]), "=r"(r[3]) : "r"(addr));
}

__device__ __forceinline__ void mma16816(float* c, const uint32_t* a,
                                         uint32_t b0, uint32_t b1) {
    asm volatile(
        "mma.sync.aligned.m16n8k16.row.col.f32.bf16.bf16.f32 "
        "{%0,%1,%2,%3}, {%4,%5,%6,%7}, {%8,%9}, {%0,%1,%2,%3};"
        : "+f"(c[0]), "+f"(c[1]), "+f"(c[2]), "+f"(c[3])
        : "r"(a[0]), "r"(a[1]), "r"(a[2]), "r"(a[3]), "r"(b0), "r"(b1));
}

__device__ __forceinline__ void mma16816h(float* c, const uint32_t* a,
                                          uint32_t b0, uint32_t b1) {
    asm volatile(
        "mma.sync.aligned.m16n8k16.row.col.f32.f16.f16.f32 "
        "{%0,%1,%2,%3}, {%4,%5,%6,%7}, {%8,%9}, {%0,%1,%2,%3};"
        : "+f"(c[0]), "+f"(c[1]), "+f"(c[2]), "+f"(c[3])
        : "r"(a[0]), "r"(a[1]), "r"(a[2]), "r"(a[3]), "r"(b0), "r"(b1));
}

__device__ __forceinline__ void bsplit(float x, __nv_bfloat16& h, __nv_bfloat16& l) {
    h = __float2bfloat16_rn(x);
    l = __float2bfloat16_rn(x - __bfloat162float(h));
}

// ---------------------------------------------------------------------------
// gemm3x (R9 body, unchanged): C = Ah@Bh^T + Ah@Bl^T + Al@Bh^T  (bf16)
// CTA 128x128, 8 warps (4m x 2n), warp 32x64, BK=32, 3-stage cp.async,
// 2 CTAs/SM. MODE 0: C0 = fp32. MODE 1: C0 = bf16 hi, C1 = bf16 lo.
// ---------------------------------------------------------------------------
#define STAGE 32768
#define NSTG  3
#define SMEM_REQ (NSTG * STAGE + 1024)

template <int MODE>
__global__ __launch_bounds__(256, 2) void gemm3x(
    const __nv_bfloat16* __restrict__ Ah, const __nv_bfloat16* __restrict__ Al,
    const __nv_bfloat16* __restrict__ Bh, const __nv_bfloat16* __restrict__ Bl,
    void* __restrict__ C0v, void* __restrict__ C1v,
    int M, int N, int K, size_t sAb, size_t sBb, size_t sCb)
{
    extern __shared__ char smem[];
    const int tid  = threadIdx.x;
    const int wid  = tid >> 5;
    const int lane = tid & 31;
    const int wm   = wid >> 1;
    const int wn   = wid & 1;
    const int m0   = blockIdx.y * 128;
    const int n0   = blockIdx.x * 128;
    const int b    = blockIdx.z;

    Ah += (size_t)b * sAb;  Al += (size_t)b * sAb;
    Bh += (size_t)b * sBb;  Bl += (size_t)b * sBb;

    uint32_t sbase = (uint32_t)__cvta_generic_to_shared(smem);
    const uint32_t ST0 = (sbase + 1023) & ~1023u;

    const int T = K >> 5;

    const int fc  = tid & 7;
    const int fr0 = tid >> 3;

    auto fill = [&](int kt, int s) {
        const uint32_t sa = ST0 + s * STAGE;
        const uint32_t sb = sa + 16384;
        const int kg = kt * 32 + (fc & 3) * 8;
#pragma unroll
        for (int i = 0; i < 4; i++) {
            int row = fr0 + i * 32;
            uint32_t so = (uint32_t)row * 128 + (uint32_t)(fc ^ (row & 7)) * 16;
            const __nv_bfloat16* ga = (fc < 4)
                ? Ah + (size_t)(m0 + row) * K + kg
                : Al + (size_t)(m0 + row) * K + kg;
            cp16(sa + so, ga);
            const __nv_bfloat16* gb = (fc < 4)
                ? Bh + (size_t)(n0 + row) * K + kg
                : Bl + (size_t)(n0 + row) * K + kg;
            cp16(sb + so, gb);
        }
        cp_commit();
    };

    float acc[2][8][4];
#pragma unroll
    for (int mt = 0; mt < 2; mt++)
#pragma unroll
        for (int nt = 0; nt < 8; nt++)
#pragma unroll
            for (int j = 0; j < 4; j++) acc[mt][nt][j] = 0.0f;

    fill(0, 0); fill(1, 1);

    int scur = 0, snext2 = 2;
    for (int kt = 0; kt < T; kt++) {
        cp_wait1();
        __syncthreads();
        if (kt + 2 < T) fill(kt + 2, snext2); else cp_commit();

        const uint32_t sa = ST0 + scur * STAGE;
        const uint32_t sb = sa + 16384;
        scur = (scur == 2) ? 0 : scur + 1;
        snext2 = (snext2 == 2) ? 0 : snext2 + 1;

#pragma unroll
        for (int k = 0; k < 2; k++) {
            const int ck = k * 2;
            const int lch = ck + (lane >> 4);
            uint32_t ah[2][4], al[2][4];
#pragma unroll
            for (int mt = 0; mt < 2; mt++) {
                int mr  = wm * 32 + mt * 16 + (lane & 15);
                uint32_t base = sa + (uint32_t)mr * 128;
                ldmx4(ah[mt], base + (uint32_t)((lch    ) ^ (mr & 7)) * 16);
                ldmx4(al[mt], base + (uint32_t)((lch + 4) ^ (mr & 7)) * 16);
            }
#pragma unroll
            for (int ng = 0; ng < 4; ng++) {
                int nr  = wn * 64 + ng * 16 + (lane & 15);
                uint32_t base = sb + (uint32_t)nr * 128;
                uint32_t bh[4], bl[4];
                ldmx4(bh, base + (uint32_t)((lch    ) ^ (nr & 7)) * 16);
                ldmx4(bl, base + (uint32_t)((lch + 4) ^ (nr & 7)) * 16);
#pragma unroll
                for (int mt = 0; mt < 2; mt++)
#pragma unroll
                    for (int o = 0; o < 2; o++) {
                        const int nt = 2 * ng + o;
                        mma16816(acc[mt][nt], ah[mt], bh[o], bh[2 + o]);
                        mma16816(acc[mt][nt], ah[mt], bl[o], bl[2 + o]);
                        mma16816(acc[mt][nt], al[mt], bh[o], bh[2 + o]);
                    }
            }
        }
    }

    const int gm0 = m0 + wm * 32;
    const int gn0 = n0 + wn * 64;
#pragma unroll
    for (int mt = 0; mt < 2; mt++) {
#pragma unroll
        for (int nt = 0; nt < 8; nt++) {
            int r  = gm0 + mt * 16 + (lane >> 2);
            int cc = gn0 + nt * 8 + 2 * (lane & 3);
            if (MODE == 0) {
                float* C0 = (float*)C0v + (size_t)b * sCb;
                *(float2*)(C0 + (size_t)r * N + cc) =
                    make_float2(acc[mt][nt][0], acc[mt][nt][1]);
                *(float2*)(C0 + (size_t)(r + 8) * N + cc) =
                    make_float2(acc[mt][nt][2], acc[mt][nt][3]);
            } else {
                __nv_bfloat16* CH = (__nv_bfloat16*)C0v + (size_t)b * sCb;
                __nv_bfloat16* CL = (__nv_bfloat16*)C1v + (size_t)b * sCb;
                __nv_bfloat16 h0, l0, h1, l1;
#pragma unroll
                for (int hh = 0; hh < 2; hh++) {
                    int rr = r + hh * 8;
                    bsplit(acc[mt][nt][2 * hh + 0], h0, l0);
                    bsplit(acc[mt][nt][2 * hh + 1], h1, l1);
                    *(__nv_bfloat162*)(CH + (size_t)rr * N + cc) =
                        __nv_bfloat162(h0, h1);
                    *(__nv_bfloat162*)(CL + (size_t)rr * N + cc) =
                        __nv_bfloat162(l0, l1);
                }
            }
        }
    }
}

// ---------------------------------------------------------------------------
// gemm1x: C[M,N] fp32 = A @ B^T, single fp16 product.
// A: [M,K] fp16, B: [N,K] fp16, K-major. CTA 128x128, 8 warps (4m x 2n),
// warp 32x64, BK=64 (row = 64 fp16 = 128B), 3-stage cp.async, 2 CTAs/SM.
// Swizzle: phys chunk = logical ^ (row&7); chunk = (lane>>4) | (ks<<1) has
// disjoint bits -> addr = base ^ (ks<<5).
// ---------------------------------------------------------------------------
__global__ __launch_bounds__(256, 2) void gemm1x(
    const __half* __restrict__ A, const __half* __restrict__ B,
    float* __restrict__ C, int M, int N, int K,
    size_t sAb, size_t sBb, size_t sCb)
{
    extern __shared__ char smem[];
    const int tid  = threadIdx.x;
    const int wid  = tid >> 5;
    const int lane = tid & 31;
    const int wm   = wid >> 1;
    const int wn   = wid & 1;
    const int m0   = blockIdx.y * 128;
    const int n0   = blockIdx.x * 128;
    const int b    = blockIdx.z;

    A += (size_t)b * sAb;
    B += (size_t)b * sBb;

    uint32_t sbase = (uint32_t)__cvta_generic_to_shared(smem);
    const uint32_t ST0 = (sbase + 1023) & ~1023u;

    const int T = K >> 6;           // chunks of 64 fp16

    const int fc  = tid & 7;        // 16B chunk 0..7 (k = fc*8..fc*8+7)
    const int fr0 = tid >> 3;       // 0..31

    auto fill = [&](int kt, int s) {
        const uint32_t sa = ST0 + s * STAGE;
        const uint32_t sb = sa + 16384;
        const int kg = kt * 64 + fc * 8;
#pragma unroll
        for (int i = 0; i < 4; i++) {
            int row = fr0 + i * 32;
            uint32_t so = (uint32_t)row * 128 + (uint32_t)(fc ^ (row & 7)) * 16;
            cp16(sa + so, A + (size_t)(m0 + row) * K + kg);
            cp16(sb + so, B + (size_t)(n0 + row) * K + kg);
        }
        cp_commit();
    };

    // precomputed ldmatrix bases (chunk bit0 = lane>>4; ks in bits 1..2)
    const uint32_t c0 = lane >> 4;
    uint32_t offA[2], offB[4];
#pragma unroll
    for (int mt = 0; mt < 2; mt++) {
        int mr = wm * 32 + mt * 16 + (lane & 15);
        offA[mt] = (uint32_t)mr * 128 + ((c0 ^ (uint32_t)(mr & 7)) * 16);
    }
#pragma unroll
    for (int ng = 0; ng < 4; ng++) {
        int nr = wn * 64 + ng * 16 + (lane & 15);
        offB[ng] = 16384u + (uint32_t)nr * 128 + ((c0 ^ (uint32_t)(nr & 7)) * 16);
    }

    float acc[2][8][4];
#pragma unroll
    for (int mt = 0; mt < 2; mt++)
#pragma unroll
        for (int nt = 0; nt < 8; nt++)
#pragma unroll
            for (int j = 0; j < 4; j++) acc[mt][nt][j] = 0.0f;

    fill(0, 0); fill(1, 1);

    int scur = 0, snext2 = 2;
    for (int kt = 0; kt < T; kt++) {
        cp_wait1();
        __syncthreads();
        if (kt + 2 < T) fill(kt + 2, snext2); else cp_commit();

        const uint32_t sa = ST0 + scur * STAGE;
        scur = (scur == 2) ? 0 : scur + 1;
        snext2 = (snext2 == 2) ? 0 : snext2 + 1;

#pragma unroll
        for (int ks = 0; ks < 4; ks++) {       // four k16 steps
            const uint32_t kx = (uint32_t)ks << 5;
            uint32_t a[2][4];
#pragma unroll
            for (int mt = 0; mt < 2; mt++)
                ldmx4(a[mt], (sa + offA[mt]) ^ kx);
#pragma unroll
            for (int ng = 0; ng < 4; ng++) {
                uint32_t bb[4];
                ldmx4(bb, (sa + offB[ng]) ^ kx);
#pragma unroll
                for (int mt = 0; mt < 2; mt++)
#pragma unroll
                    for (int o = 0; o < 2; o++)
                        mma16816h(acc[mt][2 * ng + o], a[mt], bb[o], bb[2 + o]);
            }
        }
    }

    const int gm0 = m0 + wm * 32;
    const int gn0 = n0 + wn * 64;
    float* C0 = C + (size_t)b * sCb;
#pragma unroll
    for (int mt = 0; mt < 2; mt++) {
#pragma unroll
        for (int nt = 0; nt < 8; nt++) {
            int r  = gm0 + mt * 16 + (lane >> 2);
            int cc = gn0 + nt * 8 + 2 * (lane & 3);
            *(float2*)(C0 + (size_t)r * N + cc) =
                make_float2(acc[mt][nt][0], acc[mt][nt][1]);
            *(float2*)(C0 + (size_t)(r + 8) * N + cc) =
                make_float2(acc[mt][nt][2], acc[mt][nt][3]);
        }
    }
}

// ---------------------------------------------------------------------------
// split fp32 -> bf16 hi/lo
// ---------------------------------------------------------------------------
__global__ __launch_bounds__(256) void split_bf16(
    const float* __restrict__ x, __nv_bfloat16* __restrict__ hi,
    __nv_bfloat16* __restrict__ lo, size_t n4)
{
    size_t i = (size_t)blockIdx.x * blockDim.x + threadIdx.x;
    size_t stride = (size_t)gridDim.x * blockDim.x;
    for (; i < n4; i += stride) {
        float4 v = ((const float4*)x)[i];
        __nv_bfloat16 h0, l0, h1, l1, h2, l2, h3, l3;
        bsplit(v.x, h0, l0); bsplit(v.y, h1, l1);
        bsplit(v.z, h2, l2); bsplit(v.w, h3, l3);
        ((__nv_bfloat162*)hi)[2 * i]     = __nv_bfloat162(h0, h1);
        ((__nv_bfloat162*)hi)[2 * i + 1] = __nv_bfloat162(h2, h3);
        ((__nv_bfloat162*)lo)[2 * i]     = __nv_bfloat162(l0, l1);
        ((__nv_bfloat162*)lo)[2 * i + 1] = __nv_bfloat162(l2, l3);
    }
}

// ---------------------------------------------------------------------------
// transpose to fp16: S[b][n][h] -> T[b][h][n]
// ---------------------------------------------------------------------------
__global__ __launch_bounds__(256) void transpose_f16(
    const float* __restrict__ S, __half* __restrict__ Tt)
{
    __shared__ float t[32][33];
    const int b  = blockIdx.z;
    const int h0 = blockIdx.x * 32;
    const int n0 = blockIdx.y * 32;
    const int tx = threadIdx.x, ty = threadIdx.y;
    const float* Sb = S + (size_t)b * SEQ * HDIM;
#pragma unroll
    for (int i = 0; i < 4; i++) {
        int r = ty + i * 8;
        t[r][tx] = Sb[(size_t)(n0 + r) * HDIM + h0 + tx];
    }
    __syncthreads();
    const size_t obase = (size_t)b * HDIM * SEQ;
#pragma unroll
    for (int i = 0; i < 4; i++) {
        int r = ty + i * 8;
        Tt[obase + (size_t)(h0 + r) * SEQ + n0 + tx] = __float2half_rn(t[tx][r]);
    }
}

// ---------------------------------------------------------------------------
// softmax rows (len 2048) -> fp16 probabilities
// ---------------------------------------------------------------------------
__global__ __launch_bounds__(256) void softmax_f16(
    const float* __restrict__ S, __half* __restrict__ P)
{
    const float* row = S + (size_t)blockIdx.x * SEQ;
    const int tid = threadIdx.x;
    const int lane = tid & 31, wrp = tid >> 5;
    __shared__ float red[8];

    float v[8];
    float4 v0 = *(const float4*)(row + tid * 8);
    float4 v1 = *(const float4*)(row + tid * 8 + 4);
    v[0]=v0.x; v[1]=v0.y; v[2]=v0.z; v[3]=v0.w;
    v[4]=v1.x; v[5]=v1.y; v[6]=v1.z; v[7]=v1.w;

    float m = v[0];
#pragma unroll
    for (int i = 1; i < 8; i++) m = fmaxf(m, v[i]);
#pragma unroll
    for (int o = 16; o > 0; o >>= 1) m = fmaxf(m, __shfl_xor_sync(~0u, m, o));
    if (lane == 0) red[wrp] = m;
    __syncthreads();
    m = red[0];
#pragma unroll
    for (int w = 1; w < 8; w++) m = fmaxf(m, red[w]);
    __syncthreads();

    float s = 0.0f;
#pragma unroll
    for (int i = 0; i < 8; i++) { v[i] = __expf(v[i] - m); s += v[i]; }
#pragma unroll
    for (int o = 16; o > 0; o >>= 1) s += __shfl_xor_sync(~0u, s, o);
    if (lane == 0) red[wrp] = s;
    __syncthreads();
    s = red[0];
#pragma unroll
    for (int w = 1; w < 8; w++) s += red[w];
    float inv = 1.0f / s;

    __half2* ph = (__half2*)(P + (size_t)blockIdx.x * SEQ + tid * 8);
#pragma unroll
    for (int i = 0; i < 4; i++)
        ph[i] = __floats2half2_rn(v[2 * i] * inv, v[2 * i + 1] * inv);
}

// ---------------------------------------------------------------------------
// launch — index 3 (ncu-captured) stays on gemm3x<1> (proj1).
// Hazards: shh last read @4, overwritten @9; sc last read @7, overwritten @10;
// at last read @8, overwritten @12.
// ---------------------------------------------------------------------------
extern "C" void kernel_launch(void* const* d_in, const int* in_sizes, int n_in,
                              void* d_out, int out_size)
{
    const float* S1 = (const float*)d_in[0];
    const float* S2 = (const float*)d_in[1];
    const float* W1 = (const float*)d_in[2];
    const float* W2 = (const float*)d_in[3];

    float* out1 = (float*)d_out;
    float* out2 = out1 + E1;

    __nv_bfloat16 *s1h, *s1l, *s2h, *s2l, *w1h, *w1l, *w2h, *w2l, *shh, *shl;
    __half *s1t, *s2t, *at;
    float* sc;
    cudaGetSymbolAddress((void**)&s1h, g_s1h);
    cudaGetSymbolAddress((void**)&s1l, g_s1l);
    cudaGetSymbolAddress((void**)&s2h, g_s2h);
    cudaGetSymbolAddress((void**)&s2l, g_s2l);
    cudaGetSymbolAddress((void**)&w1h, g_w1h);
    cudaGetSymbolAddress((void**)&w1l, g_w1l);
    cudaGetSymbolAddress((void**)&w2h, g_w2h);
    cudaGetSymbolAddress((void**)&w2l, g_w2l);
    cudaGetSymbolAddress((void**)&shh, g_shh);
    cudaGetSymbolAddress((void**)&shl, g_shl);
    cudaGetSymbolAddress((void**)&s1t, g_s1t);
    cudaGetSymbolAddress((void**)&s2t, g_s2t);
    cudaGetSymbolAddress((void**)&sc,  g_sc);
    cudaGetSymbolAddress((void**)&at,  g_at);

    cudaFuncSetAttribute(gemm3x<0>, cudaFuncAttributeMaxDynamicSharedMemorySize, SMEM_REQ);
    cudaFuncSetAttribute(gemm3x<1>, cudaFuncAttributeMaxDynamicSharedMemorySize, SMEM_REQ);
    cudaFuncSetAttribute(gemm1x,    cudaFuncAttributeMaxDynamicSharedMemorySize, SMEM_REQ);

    const size_t sS  = (size_t)SEQ * HDIM;
    const size_t sSc = (size_t)SEQ * SEQ;

    dim3 blk(256);
    dim3 gProj(HDIM / 128, SEQ / 128, BATCH);   // N=1024, M=2048
    dim3 gScore(SEQ / 128, SEQ / 128, BATCH);   // N=2048, M=2048
    dim3 gPV(HDIM / 128, SEQ / 128, BATCH);     // N=1024, M=2048, K=2048
    dim3 tb(32, 8);
    dim3 tg(HDIM / 32, SEQ / 32, BATCH);

    split_bf16<<<2048, 256>>>(S2, s2h, s2l, E1 / 4);                 // 0
    split_bf16<<<512,  256>>>(W1, w1h, w1l, EW / 4);                 // 1
    split_bf16<<<2048, 256>>>(S1, s1h, s1l, E1 / 4);                 // 2

    gemm3x<1><<<gProj, blk, SMEM_REQ>>>(                             // 3 (ncu)
        s2h, s2l, w1h, w1l, shh, shl, SEQ, HDIM, HDIM, sS, 0, sS);
    gemm3x<0><<<gScore, blk, SMEM_REQ>>>(                            // 4
        s1h, s1l, shh, shl, sc, nullptr, SEQ, SEQ, HDIM, sS, sS, sSc);

    split_bf16<<<512,  256>>>(W2, w2h, w2l, EW / 4);                 // 5
    transpose_f16<<<tg, tb>>>(S2, s2t);                              // 6
    softmax_f16<<<BATCH * SEQ, 256>>>(sc, at);                       // 7
    gemm1x<<<gPV, blk, SMEM_REQ>>>(                                  // 8
        at, s2t, out1, SEQ, HDIM, SEQ, sSc, sS, sS);

    gemm3x<1><<<gProj, blk, SMEM_REQ>>>(                             // 9
        s1h, s1l, w2h, w2l, shh, shl, SEQ, HDIM, HDIM, sS, 0, sS);
    gemm3x<0><<<gScore, blk, SMEM_REQ>>>(                            // 10
        s2h, s2l, shh, shl, sc, nullptr, SEQ, SEQ, HDIM, sS, sS, sSc);
    transpose_f16<<<tg, tb>>>(S1, s1t);                              // 11
    softmax_f16<<<BATCH * SEQ, 256>>>(sc, at);                       // 12
    gemm1x<<<gPV, blk, SMEM_REQ>>>(                                  // 13
        at, s1t, out2, SEQ, HDIM, SEQ, sSc, sS, sS);
}